// round 10
// baseline (speedup 1.0000x reference)
#include <cuda_runtime.h>
#include <cuda_bf16.h>
#include <cstdint>

#define B_ 4
#define T_ 1024
#define E_ 512
#define H_ 64
#define DK 8

typedef unsigned long long ull;

__device__ float g_attn[B_ * T_ * E_];

__device__ __forceinline__ float ex2_approx(float s) {
    float e;
    asm("ex2.approx.ftz.f32 %0, %1;" : "=f"(e) : "f"(s));
    return e;
}
// exp2 on the FMA pipe: |s| <= 4.1. round-to-int magic + deg-4 Taylor (err ~4e-5).
__device__ __forceinline__ float exp2_poly(float s) {
    float t = s + 12582912.0f;                 // 1.5 * 2^23
    int i = __float_as_int(t) - 0x4B400000;    // round(s)
    float r = s - (t - 12582912.0f);           // r in [-0.5, 0.5]
    float p = 0.00961812f;
    p = fmaf(p, r, 0.0555041f);
    p = fmaf(p, r, 0.240227f);
    p = fmaf(p, r, 0.693147f);
    p = fmaf(p, r, 1.0f);
    return __int_as_float(__float_as_int(p) + (i << 23));
}
__device__ __forceinline__ uint32_t bf2(float lo, float hi) {
    uint32_t r;
    asm("cvt.rn.bf16x2.f32 %0, %1, %2;" : "=r"(r) : "f"(hi), "f"(lo));
    return r;
}
__device__ __forceinline__ uint32_t tf32r(float f) {
    uint32_t u;
    asm("cvt.rna.tf32.f32 %0, %1;" : "=r"(u) : "f"(f));
    return u;
}
__device__ __forceinline__ uint32_t smem_u32(const void* p) {
    uint32_t a;
    asm("{ .reg .u64 t; cvta.to.shared.u64 t, %1; cvt.u32.u64 %0, t; }" : "=r"(a) : "l"(p));
    return a;
}
__device__ __forceinline__ void ldsm_x2(uint32_t& r0, uint32_t& r1, uint32_t a) {
    asm volatile("ldmatrix.sync.aligned.m8n8.x2.shared.b16 {%0,%1}, [%2];"
                 : "=r"(r0), "=r"(r1) : "r"(a));
}
__device__ __forceinline__ void ldsm_x2t(uint32_t& r0, uint32_t& r1, uint32_t a) {
    asm volatile("ldmatrix.sync.aligned.m8n8.x2.trans.shared.b16 {%0,%1}, [%2];"
                 : "=r"(r0), "=r"(r1) : "r"(a));
}
__device__ __forceinline__ void mma_k8(float c[4], uint32_t a0, uint32_t a1, uint32_t b0) {
    asm volatile("mma.sync.aligned.m16n8k8.row.col.f32.bf16.bf16.f32 "
                 "{%0,%1,%2,%3}, {%4,%5}, {%6}, {%0,%1,%2,%3};"
                 : "+f"(c[0]), "+f"(c[1]), "+f"(c[2]), "+f"(c[3])
                 : "r"(a0), "r"(a1), "r"(b0));
}
__device__ __forceinline__ void mma_k16(float c[4], uint32_t a0, uint32_t a1,
                                        uint32_t a2, uint32_t a3,
                                        uint32_t b0, uint32_t b1) {
    asm volatile("mma.sync.aligned.m16n8k16.row.col.f32.bf16.bf16.f32 "
                 "{%0,%1,%2,%3}, {%4,%5,%6,%7}, {%8,%9}, {%0,%1,%2,%3};"
                 : "+f"(c[0]), "+f"(c[1]), "+f"(c[2]), "+f"(c[3])
                 : "r"(a0), "r"(a1), "r"(a2), "r"(a3), "r"(b0), "r"(b1));
}
__device__ __forceinline__ void mma_tf32(float c[4], uint32_t a0, uint32_t a1,
                                         uint32_t a2, uint32_t a3,
                                         uint32_t b0, uint32_t b1) {
    asm volatile("mma.sync.aligned.m16n8k8.row.col.f32.tf32.tf32.f32 "
                 "{%0,%1,%2,%3}, {%4,%5,%6,%7}, {%8,%9}, {%0,%1,%2,%3};"
                 : "+f"(c[0]), "+f"(c[1]), "+f"(c[2]), "+f"(c[3])
                 : "r"(a0), "r"(a1), "r"(a2), "r"(a3), "r"(b0), "r"(b1));
}

// ============================================================================
// Kernel 1: tensor-core attention (R8 structure). Hybrid softmax exp:
// 5 of 8 exps on MUFU (ex2.approx), 3 on the FMA pipe (exp2_poly) so the
// two pipes run concurrently (EX2 was the binding floor).
// ============================================================================
__global__ __launch_bounds__(256)
void qattn_mma(const float* __restrict__ x, const float* __restrict__ theta) {
    __shared__ __align__(16) __nv_bfloat16 Ps[T_][DK];
    __shared__ __align__(16) __nv_bfloat16 Pv[T_][DK];
    __shared__ float cth[DK];

    const int tid  = threadIdx.x;
    const int lane = tid & 31;
    const int warp = tid >> 5;
    const int qt   = blockIdx.x & 7;
    const int bh   = blockIdx.x >> 3;
    const int b    = bh >> 6;
    const int h    = bh & 63;

    if (tid < DK) cth[tid] = __cosf(theta[tid]);
    __syncthreads();

    const float S1 = 0.714215694f;  // sqrt((1/sqrt(8)) * log2(e))
    const float* xb = x + ((size_t)b * T_) * E_ + h * DK;
    #pragma unroll
    for (int i = 0; i < 4; i++) {
        int t = i * 256 + tid;
        float4 v0 = *(const float4*)(xb + (size_t)t * E_);
        float4 v1 = *(const float4*)(xb + (size_t)t * E_ + 4);
        float c[8];
        c[0] = __cosf(v0.x) * cth[0]; c[1] = __cosf(v0.y) * cth[1];
        c[2] = __cosf(v0.z) * cth[2]; c[3] = __cosf(v0.w) * cth[3];
        c[4] = __cosf(v1.x) * cth[4]; c[5] = __cosf(v1.y) * cth[5];
        c[6] = __cosf(v1.z) * cth[6]; c[7] = __cosf(v1.w) * cth[7];
        uint4 ps, pv;
        ps.x = bf2(S1 * c[0], S1 * c[1]); ps.y = bf2(S1 * c[2], S1 * c[3]);
        ps.z = bf2(S1 * c[4], S1 * c[5]); ps.w = bf2(S1 * c[6], S1 * c[7]);
        pv.x = bf2(c[0], c[1]); pv.y = bf2(c[2], c[3]);
        pv.z = bf2(c[4], c[5]); pv.w = bf2(c[6], c[7]);
        *(uint4*)&Ps[t][0] = ps;
        *(uint4*)&Pv[t][0] = pv;
    }
    __syncthreads();

    const int qbase = qt * 128 + warp * 16;
    uint32_t qa0, qa1;
    ldsm_x2(qa0, qa1, smem_u32(&Ps[qbase + (lane & 15)][0]));

    float o[4] = {0.f, 0.f, 0.f, 0.f};
    float l0 = 0.f, l1 = 0.f;

    for (int k0 = 0; k0 < T_; k0 += 16) {
        uint32_t kb0, kb1, vb0, vb1;
        ldsm_x2(kb0, kb1, smem_u32(&Ps[k0 + (lane & 15)][0]));
        ldsm_x2t(vb0, vb1, smem_u32(&Pv[k0 + (lane & 15)][0]));

        float c0[4] = {0.f, 0.f, 0.f, 0.f};
        float c1[4] = {0.f, 0.f, 0.f, 0.f};
        mma_k8(c0, qa0, qa1, kb0);
        mma_k8(c1, qa0, qa1, kb1);

        // Hybrid exp: split across MUFU (ex2) and FMA (poly) pipes.
        float e00 = ex2_approx(c0[0]), e01 = exp2_poly(c0[1]);
        float e02 = ex2_approx(c0[2]), e03 = exp2_poly(c0[3]);
        float e10 = ex2_approx(c1[0]), e11 = exp2_poly(c1[1]);
        float e12 = ex2_approx(c1[2]), e13 = ex2_approx(c1[3]);
        l0 += (e00 + e01) + (e10 + e11);
        l1 += (e02 + e03) + (e12 + e13);

        uint32_t p0 = bf2(e00, e01), p1 = bf2(e02, e03);
        uint32_t p2 = bf2(e10, e11), p3 = bf2(e12, e13);
        mma_k16(o, p0, p1, p2, p3, vb0, vb1);
    }

    l0 += __shfl_xor_sync(0xFFFFFFFFu, l0, 1);
    l0 += __shfl_xor_sync(0xFFFFFFFFu, l0, 2);
    l1 += __shfl_xor_sync(0xFFFFFFFFu, l1, 1);
    l1 += __shfl_xor_sync(0xFFFFFFFFu, l1, 2);
    float inv0 = 1.0f / l0, inv1 = 1.0f / l1;

    const int q0 = qbase + (lane >> 2);
    const int col = h * DK + ((lane & 3) << 1);
    float* p0 = g_attn + ((size_t)(b * T_ + q0)) * E_ + col;
    float* p1 = g_attn + ((size_t)(b * T_ + q0 + 8)) * E_ + col;
    *(float2*)p0 = make_float2(o[0] * inv0, o[1] * inv0);
    *(float2*)p1 = make_float2(o[2] * inv1, o[3] * inv1);
}

// ============================================================================
// Kernel 2: tf32 combine GEMM, packed-fragment SMEM + double buffering.
// CTA 128m x 64n, 256 thr, 8 warps (4x2), warp = 32x32.
// PA layout: word = (mb*2+kb)*208 + c*24 + g*2 + sel  (A[mb*16+sel*8+g][kb*8+c])
// PB layout: word = (nb*2+kb)*68  + g*8  + tg*2 + sel (W[nb*8+g][kb*8+tg+sel*4])
// -> every fragment half is one conflict-free LDS.64. One sync per k16 chunk.
// ============================================================================
#define PA_SZ 3328   // 8 mb * 2 kb * 208
#define PB_SZ 1088   // 8 nb * 2 kb * 68
__global__ __launch_bounds__(256)
void combine_tf32(const float* __restrict__ W, const float* __restrict__ bias,
                  float* __restrict__ C) {
    __shared__ __align__(16) uint32_t PA[2][PA_SZ];
    __shared__ __align__(16) uint32_t PB[2][PB_SZ];

    const int tid  = threadIdx.x;
    const int lane = tid & 31;
    const int warp = tid >> 5;
    const int g    = lane >> 2;
    const int tg   = lane & 3;
    const int row0 = blockIdx.y * 128;
    const int col0 = blockIdx.x * 64;
    const int mw   = warp >> 1;
    const int nw   = warp & 1;

    // Load mapping.
    const int ar = tid >> 1, akb = tid & 1;          // A row, k8-block
    const int wr = tid >> 2, wq = tid & 3;           // W row, k4-quarter
    const int wkb = wq >> 1, wsel = wq & 1;          // W k8-block, half
    const float* Ap = g_attn + (size_t)(row0 + ar) * E_ + akb * 8;
    const float* Wp = W      + (size_t)(col0 + wr) * E_ + wq * 4;

    // Precomputed store bases.
    const int a_base = ((ar >> 4) * 2 + akb) * 208 + ((ar >> 3) & 1) + (ar & 7) * 2;
    const int w_base = ((wr >> 3) * 2 + wkb) * 68 + (wr & 7) * 8 + wsel;

    float acc[2][4][4];
    #pragma unroll
    for (int mi = 0; mi < 2; mi++)
        #pragma unroll
        for (int ni = 0; ni < 4; ni++)
            #pragma unroll
            for (int j = 0; j < 4; j++) acc[mi][ni][j] = 0.f;

    float4 ra0 = *(const float4*)(Ap);
    float4 ra1 = *(const float4*)(Ap + 4);
    float4 rw  = *(const float4*)(Wp);

    // Store chunk 0 into buffer 0.
    {
        float av[8] = {ra0.x, ra0.y, ra0.z, ra0.w, ra1.x, ra1.y, ra1.z, ra1.w};
        #pragma unroll
        for (int j = 0; j < 8; j++) PA[0][a_base + j * 24] = tf32r(av[j]);
        float wv[4] = {rw.x, rw.y, rw.z, rw.w};
        #pragma unroll
        for (int j = 0; j < 4; j++) PB[0][w_base + j * 2] = tf32r(wv[j]);
    }
    __syncthreads();

    for (int ch = 0; ch < E_ / 16; ch++) {
        const int buf = ch & 1;
        const bool more = (ch + 1) < E_ / 16;
        if (more) {
            ra0 = *(const float4*)(Ap + (ch + 1) * 16);
            ra1 = *(const float4*)(Ap + (ch + 1) * 16 + 4);
            rw  = *(const float4*)(Wp + (ch + 1) * 16);
        }

        const uint32_t* pa = PA[buf];
        const uint32_t* pb = PB[buf];
        #pragma unroll
        for (int kb = 0; kb < 2; kb++) {
            ull ap1[2], ap2[2], bp[4];
            #pragma unroll
            for (int mi = 0; mi < 2; mi++) {
                int ab = ((2 * mw + mi) * 2 + kb) * 208 + tg * 24 + g * 2;
                ap1[mi] = *(const ull*)&pa[ab];        // a0,a1
                ap2[mi] = *(const ull*)&pa[ab + 96];   // a2,a3
            }
            #pragma unroll
            for (int ni = 0; ni < 4; ni++) {
                int bb = ((4 * nw + ni) * 2 + kb) * 68 + g * 8 + tg * 2;
                bp[ni] = *(const ull*)&pb[bb];         // b0,b1
            }
            #pragma unroll
            for (int ni = 0; ni < 4; ni++) {
                uint32_t b0 = (uint32_t)bp[ni], b1 = (uint32_t)(bp[ni] >> 32);
                #pragma unroll
                for (int mi = 0; mi < 2; mi++) {
                    uint32_t a0 = (uint32_t)ap1[mi], a1 = (uint32_t)(ap1[mi] >> 32);
                    uint32_t a2 = (uint32_t)ap2[mi], a3 = (uint32_t)(ap2[mi] >> 32);
                    mma_tf32(acc[mi][ni], a0, a1, a2, a3, b0, b1);
                }
            }
        }

        if (more) {
            const int nb = buf ^ 1;
            float av[8] = {ra0.x, ra0.y, ra0.z, ra0.w, ra1.x, ra1.y, ra1.z, ra1.w};
            #pragma unroll
            for (int j = 0; j < 8; j++) PA[nb][a_base + j * 24] = tf32r(av[j]);
            float wv[4] = {rw.x, rw.y, rw.z, rw.w};
            #pragma unroll
            for (int j = 0; j < 4; j++) PB[nb][w_base + j * 2] = tf32r(wv[j]);
        }
        __syncthreads();
    }

    #pragma unroll
    for (int mi = 0; mi < 2; mi++) {
        int row = row0 + mw * 32 + mi * 16 + g;
        #pragma unroll
        for (int ni = 0; ni < 4; ni++) {
            int c = col0 + nw * 32 + ni * 8 + (tg << 1);
            float2 bi = *(const float2*)&bias[c];
            *(float2*)&C[(size_t)row * E_ + c] =
                make_float2(acc[mi][ni][0] + bi.x, acc[mi][ni][1] + bi.y);
            *(float2*)&C[(size_t)(row + 8) * E_ + c] =
                make_float2(acc[mi][ni][2] + bi.x, acc[mi][ni][3] + bi.y);
        }
    }
}

extern "C" void kernel_launch(void* const* d_in, const int* in_sizes, int n_in,
                              void* d_out, int out_size) {
    const float* x     = (const float*)d_in[0];
    const float* theta = (const float*)d_in[1];
    const float* W     = (const float*)d_in[2];
    const float* bias  = (const float*)d_in[3];
    float* out = (float*)d_out;

    qattn_mma<<<B_ * H_ * 8, 256>>>(x, theta);
    dim3 g2(E_ / 64, (B_ * T_) / 128);
    combine_tf32<<<g2, 256>>>(W, bias, out);
}

// round 11
// speedup vs baseline: 1.1277x; 1.1277x over previous
#include <cuda_runtime.h>
#include <cuda_bf16.h>
#include <cstdint>

#define B_ 4
#define T_ 1024
#define E_ 512
#define H_ 64
#define DK 8

typedef unsigned long long ull;

__device__ float g_attn[B_ * T_ * E_];

__device__ __forceinline__ float ex2_approx(float s) {
    float e;
    asm("ex2.approx.ftz.f32 %0, %1;" : "=f"(e) : "f"(s));
    return e;
}
__device__ __forceinline__ uint32_t bf2(float lo, float hi) {
    uint32_t r;
    asm("cvt.rn.bf16x2.f32 %0, %1, %2;" : "=r"(r) : "f"(hi), "f"(lo));
    return r;
}
__device__ __forceinline__ uint32_t tf32r(float f) {
    uint32_t u;
    asm("cvt.rna.tf32.f32 %0, %1;" : "=r"(u) : "f"(f));
    return u;
}
__device__ __forceinline__ uint32_t smem_u32(const void* p) {
    uint32_t a;
    asm("{ .reg .u64 t; cvta.to.shared.u64 t, %1; cvt.u32.u64 %0, t; }" : "=r"(a) : "l"(p));
    return a;
}
__device__ __forceinline__ void ldsm_x2(uint32_t& r0, uint32_t& r1, uint32_t a) {
    asm volatile("ldmatrix.sync.aligned.m8n8.x2.shared.b16 {%0,%1}, [%2];"
                 : "=r"(r0), "=r"(r1) : "r"(a));
}
__device__ __forceinline__ void ldsm_x2t(uint32_t& r0, uint32_t& r1, uint32_t a) {
    asm volatile("ldmatrix.sync.aligned.m8n8.x2.trans.shared.b16 {%0,%1}, [%2];"
                 : "=r"(r0), "=r"(r1) : "r"(a));
}
__device__ __forceinline__ void mma_k8(float c[4], uint32_t a0, uint32_t a1, uint32_t b0) {
    asm volatile("mma.sync.aligned.m16n8k8.row.col.f32.bf16.bf16.f32 "
                 "{%0,%1,%2,%3}, {%4,%5}, {%6}, {%0,%1,%2,%3};"
                 : "+f"(c[0]), "+f"(c[1]), "+f"(c[2]), "+f"(c[3])
                 : "r"(a0), "r"(a1), "r"(b0));
}
__device__ __forceinline__ void mma_k16(float c[4], uint32_t a0, uint32_t a1,
                                        uint32_t a2, uint32_t a3,
                                        uint32_t b0, uint32_t b1) {
    asm volatile("mma.sync.aligned.m16n8k16.row.col.f32.bf16.bf16.f32 "
                 "{%0,%1,%2,%3}, {%4,%5,%6,%7}, {%8,%9}, {%0,%1,%2,%3};"
                 : "+f"(c[0]), "+f"(c[1]), "+f"(c[2]), "+f"(c[3])
                 : "r"(a0), "r"(a1), "r"(a2), "r"(a3), "r"(b0), "r"(b1));
}
__device__ __forceinline__ void mma_tf32(float c[4], uint32_t a0, uint32_t a1,
                                         uint32_t a2, uint32_t a3,
                                         uint32_t b0, uint32_t b1) {
    asm volatile("mma.sync.aligned.m16n8k8.row.col.f32.tf32.tf32.f32 "
                 "{%0,%1,%2,%3}, {%4,%5,%6,%7}, {%8,%9}, {%0,%1,%2,%3};"
                 : "+f"(c[0]), "+f"(c[1]), "+f"(c[2]), "+f"(c[3])
                 : "r"(a0), "r"(a1), "r"(a2), "r"(a3), "r"(b0), "r"(b1));
}

// ============================================================================
// Kernel 1: tensor-core attention via mma.sync — EXACT R8 body (proven 56us,
// at the EX2/MUFU pipe floor; R10's poly hybrid regressed and is reverted).
// ============================================================================
__global__ __launch_bounds__(256)
void qattn_mma(const float* __restrict__ x, const float* __restrict__ theta) {
    __shared__ __align__(16) __nv_bfloat16 Ps[T_][DK];
    __shared__ __align__(16) __nv_bfloat16 Pv[T_][DK];
    __shared__ float cth[DK];

    const int tid  = threadIdx.x;
    const int lane = tid & 31;
    const int warp = tid >> 5;
    const int qt   = blockIdx.x & 7;
    const int bh   = blockIdx.x >> 3;
    const int b    = bh >> 6;
    const int h    = bh & 63;

    if (tid < DK) cth[tid] = __cosf(theta[tid]);
    __syncthreads();

    const float S1 = 0.714215694f;  // sqrt((1/sqrt(8)) * log2(e))
    const float* xb = x + ((size_t)b * T_) * E_ + h * DK;
    #pragma unroll
    for (int i = 0; i < 4; i++) {
        int t = i * 256 + tid;
        float4 v0 = *(const float4*)(xb + (size_t)t * E_);
        float4 v1 = *(const float4*)(xb + (size_t)t * E_ + 4);
        float c[8];
        c[0] = __cosf(v0.x) * cth[0]; c[1] = __cosf(v0.y) * cth[1];
        c[2] = __cosf(v0.z) * cth[2]; c[3] = __cosf(v0.w) * cth[3];
        c[4] = __cosf(v1.x) * cth[4]; c[5] = __cosf(v1.y) * cth[5];
        c[6] = __cosf(v1.z) * cth[6]; c[7] = __cosf(v1.w) * cth[7];
        uint4 ps, pv;
        ps.x = bf2(S1 * c[0], S1 * c[1]); ps.y = bf2(S1 * c[2], S1 * c[3]);
        ps.z = bf2(S1 * c[4], S1 * c[5]); ps.w = bf2(S1 * c[6], S1 * c[7]);
        pv.x = bf2(c[0], c[1]); pv.y = bf2(c[2], c[3]);
        pv.z = bf2(c[4], c[5]); pv.w = bf2(c[6], c[7]);
        *(uint4*)&Ps[t][0] = ps;
        *(uint4*)&Pv[t][0] = pv;
    }
    __syncthreads();

    const int qbase = qt * 128 + warp * 16;
    uint32_t qa0, qa1;
    ldsm_x2(qa0, qa1, smem_u32(&Ps[qbase + (lane & 15)][0]));

    float o[4] = {0.f, 0.f, 0.f, 0.f};
    float l0 = 0.f, l1 = 0.f;

    for (int k0 = 0; k0 < T_; k0 += 16) {
        uint32_t kb0, kb1, vb0, vb1;
        ldsm_x2(kb0, kb1, smem_u32(&Ps[k0 + (lane & 15)][0]));
        ldsm_x2t(vb0, vb1, smem_u32(&Pv[k0 + (lane & 15)][0]));

        float c0[4] = {0.f, 0.f, 0.f, 0.f};
        float c1[4] = {0.f, 0.f, 0.f, 0.f};
        mma_k8(c0, qa0, qa1, kb0);
        mma_k8(c1, qa0, qa1, kb1);

        float e00 = ex2_approx(c0[0]), e01 = ex2_approx(c0[1]);
        float e02 = ex2_approx(c0[2]), e03 = ex2_approx(c0[3]);
        float e10 = ex2_approx(c1[0]), e11 = ex2_approx(c1[1]);
        float e12 = ex2_approx(c1[2]), e13 = ex2_approx(c1[3]);
        l0 += (e00 + e01) + (e10 + e11);
        l1 += (e02 + e03) + (e12 + e13);

        uint32_t p0 = bf2(e00, e01), p1 = bf2(e02, e03);
        uint32_t p2 = bf2(e10, e11), p3 = bf2(e12, e13);
        mma_k16(o, p0, p1, p2, p3, vb0, vb1);
    }

    l0 += __shfl_xor_sync(0xFFFFFFFFu, l0, 1);
    l0 += __shfl_xor_sync(0xFFFFFFFFu, l0, 2);
    l1 += __shfl_xor_sync(0xFFFFFFFFu, l1, 1);
    l1 += __shfl_xor_sync(0xFFFFFFFFu, l1, 2);
    float inv0 = 1.0f / l0, inv1 = 1.0f / l1;

    const int q0 = qbase + (lane >> 2);
    const int col = h * DK + ((lane & 3) << 1);
    float* p0 = g_attn + ((size_t)(b * T_ + q0)) * E_ + col;
    float* p1 = g_attn + ((size_t)(b * T_ + q0 + 8)) * E_ + col;
    *(float2*)p0 = make_float2(o[0] * inv0, o[1] * inv0);
    *(float2*)p1 = make_float2(o[2] * inv1, o[3] * inv1);
}

// ============================================================================
// Kernel 2: tf32 combine GEMM, 64x64 CTA tile / 128 threads (4 warps, 2x2,
// 32x32 per warp) for ~3x more resident CTAs than R10's 128x64 (grid 512,
// smem 22KB). Same proven packed-fragment layout (every frag half = LDS.64):
// PA word = (mb*2+kb)*208 + c*24 + g*2 + sel   (A[mb*16+sel*8+g][kb*8+c])
// PB word = (nb*2+kb)*68 + g*8 + tg*2 + sel    (W[nb*8+g][kb*8+tg+sel*4])
// Double-buffered, one __syncthreads per k16 chunk, LDG register prefetch.
// ============================================================================
#define PA_SZ 1664   // 4 mb * 2 kb * 208
#define PB_SZ 1088   // 8 nb * 2 kb * 68
__global__ __launch_bounds__(128)
void combine_tf32(const float* __restrict__ W, const float* __restrict__ bias,
                  float* __restrict__ C) {
    __shared__ __align__(16) uint32_t PA[2][PA_SZ];
    __shared__ __align__(16) uint32_t PB[2][PB_SZ];

    const int tid  = threadIdx.x;
    const int lane = tid & 31;
    const int warp = tid >> 5;
    const int g    = lane >> 2;
    const int tg   = lane & 3;
    const int row0 = blockIdx.y * 64;
    const int col0 = blockIdx.x * 64;
    const int mw   = warp >> 1;   // 0..1
    const int nw   = warp & 1;    // 0..1

    // Loads: each thread brings 8 A floats + 8 W floats per k16 chunk.
    const int ar = tid >> 1, akb = tid & 1;   // A row 0..63, k8-block
    const int wr = tid >> 1, wkb = tid & 1;   // W row 0..63, k8-block
    const float* Ap = g_attn + (size_t)(row0 + ar) * E_ + akb * 8;
    const float* Wp = W      + (size_t)(col0 + wr) * E_ + wkb * 8;

    const int a_base = ((ar >> 4) * 2 + akb) * 208 + ((ar >> 3) & 1) + (ar & 7) * 2;
    const int w_base = ((wr >> 3) * 2 + wkb) * 68 + (wr & 7) * 8;

    float acc[2][4][4];
    #pragma unroll
    for (int mi = 0; mi < 2; mi++)
        #pragma unroll
        for (int ni = 0; ni < 4; ni++)
            #pragma unroll
            for (int j = 0; j < 4; j++) acc[mi][ni][j] = 0.f;

    float4 ra0 = *(const float4*)(Ap);
    float4 ra1 = *(const float4*)(Ap + 4);
    float4 rw0 = *(const float4*)(Wp);
    float4 rw1 = *(const float4*)(Wp + 4);

    // Stage chunk 0 into buffer 0.
    {
        float av[8] = {ra0.x, ra0.y, ra0.z, ra0.w, ra1.x, ra1.y, ra1.z, ra1.w};
        #pragma unroll
        for (int j = 0; j < 8; j++) PA[0][a_base + j * 24] = tf32r(av[j]);
        float wv[8] = {rw0.x, rw0.y, rw0.z, rw0.w, rw1.x, rw1.y, rw1.z, rw1.w};
        #pragma unroll
        for (int c = 0; c < 8; c++)
            PB[0][w_base + (c >> 2) + (c & 3) * 2] = tf32r(wv[c]);
    }
    __syncthreads();

    for (int ch = 0; ch < E_ / 16; ch++) {
        const int buf = ch & 1;
        const bool more = (ch + 1) < E_ / 16;
        if (more) {
            ra0 = *(const float4*)(Ap + (ch + 1) * 16);
            ra1 = *(const float4*)(Ap + (ch + 1) * 16 + 4);
            rw0 = *(const float4*)(Wp + (ch + 1) * 16);
            rw1 = *(const float4*)(Wp + (ch + 1) * 16 + 4);
        }

        const uint32_t* pa = PA[buf];
        const uint32_t* pb = PB[buf];
        #pragma unroll
        for (int kb = 0; kb < 2; kb++) {
            ull ap1[2], ap2[2], bp[4];
            #pragma unroll
            for (int mi = 0; mi < 2; mi++) {
                int ab = ((2 * mw + mi) * 2 + kb) * 208 + tg * 24 + g * 2;
                ap1[mi] = *(const ull*)&pa[ab];        // a0,a1
                ap2[mi] = *(const ull*)&pa[ab + 96];   // a2,a3
            }
            #pragma unroll
            for (int ni = 0; ni < 4; ni++) {
                int bb = ((4 * nw + ni) * 2 + kb) * 68 + g * 8 + tg * 2;
                bp[ni] = *(const ull*)&pb[bb];         // b0,b1
            }
            #pragma unroll
            for (int ni = 0; ni < 4; ni++) {
                uint32_t b0 = (uint32_t)bp[ni], b1 = (uint32_t)(bp[ni] >> 32);
                #pragma unroll
                for (int mi = 0; mi < 2; mi++) {
                    uint32_t a0 = (uint32_t)ap1[mi], a1 = (uint32_t)(ap1[mi] >> 32);
                    uint32_t a2 = (uint32_t)ap2[mi], a3 = (uint32_t)(ap2[mi] >> 32);
                    mma_tf32(acc[mi][ni], a0, a1, a2, a3, b0, b1);
                }
            }
        }

        if (more) {
            const int nb = buf ^ 1;
            float av[8] = {ra0.x, ra0.y, ra0.z, ra0.w, ra1.x, ra1.y, ra1.z, ra1.w};
            #pragma unroll
            for (int j = 0; j < 8; j++) PA[nb][a_base + j * 24] = tf32r(av[j]);
            float wv[8] = {rw0.x, rw0.y, rw0.z, rw0.w, rw1.x, rw1.y, rw1.z, rw1.w};
            #pragma unroll
            for (int c = 0; c < 8; c++)
                PB[nb][w_base + (c >> 2) + (c & 3) * 2] = tf32r(wv[c]);
        }
        __syncthreads();
    }

    #pragma unroll
    for (int mi = 0; mi < 2; mi++) {
        int row = row0 + mw * 32 + mi * 16 + g;
        #pragma unroll
        for (int ni = 0; ni < 4; ni++) {
            int c = col0 + nw * 32 + ni * 8 + (tg << 1);
            float2 bi = *(const float2*)&bias[c];
            *(float2*)&C[(size_t)row * E_ + c] =
                make_float2(acc[mi][ni][0] + bi.x, acc[mi][ni][1] + bi.y);
            *(float2*)&C[(size_t)(row + 8) * E_ + c] =
                make_float2(acc[mi][ni][2] + bi.x, acc[mi][ni][3] + bi.y);
        }
    }
}

extern "C" void kernel_launch(void* const* d_in, const int* in_sizes, int n_in,
                              void* d_out, int out_size) {
    const float* x     = (const float*)d_in[0];
    const float* theta = (const float*)d_in[1];
    const float* W     = (const float*)d_in[2];
    const float* bias  = (const float*)d_in[3];
    float* out = (float*)d_out;

    qattn_mma<<<B_ * H_ * 8, 256>>>(x, theta);
    dim3 g2(E_ / 64, (B_ * T_) / 64);
    combine_tf32<<<g2, 128>>>(W, bias, out);
}